// round 1
// baseline (speedup 1.0000x reference)
#include <cuda_runtime.h>
#include <math.h>

// Problem: batched Stiefel optimizer step.
// N=128 batches, each M/G/U is [R=2304, C=256] row-major fp32.
// out[b] = (Q * sgn).T  where Q,Rm = qr(M + P), P = -|lr|*s*(U + G),
//          G = Graw - M @ sym(M^T Graw).
// Implemented via Cholesky-QR: S = B^T B = R^T R (R upper, positive diag ==
// sign-fixed R), Q = B R^{-1}. Positive-diag Cholesky reproduces the
// reference's sign fix exactly.

#define NB 128
#define RR 2304
#define CC 256

// Scratch (module-load device globals; sanctioned scratch mechanism)
__device__ float g_A[(size_t)NB * CC * CC];     // A = M^T Graw, later S = B^T B
__device__ float g_Asym[(size_t)NB * CC * CC];  // sym(A)
__device__ float g_Bm[(size_t)NB * RR * CC];    // B = M + P
__device__ float g_V[(size_t)NB * CC * CC];     // V = R^{-1} dense (upper tri)

// ---------------------------------------------------------------------------
// TN GEMM: C[i][j] = sum_{k=0}^{RR-1} A[k][i] * B[k][j]   (C is 256x256)
// Used for A = M^T Graw and S = B^T B. Block: 64x64 tile, 256 thr, 4x4/thread.
// ---------------------------------------------------------------------------
__global__ void k_gemm_tn(const float* __restrict__ Aop,
                          const float* __restrict__ Bop,
                          float* __restrict__ Cout)
{
    int b = blockIdx.z;
    const float* Ap = Aop + (size_t)b * RR * CC;
    const float* Bp = Bop + (size_t)b * RR * CC;
    float* Cp = Cout + (size_t)b * CC * CC;
    int i0 = blockIdx.y * 64, j0 = blockIdx.x * 64;

    __shared__ float As[32][65];
    __shared__ float Bs[32][65];

    int tid = threadIdx.x;
    int tx = tid & 15, ty = tid >> 4;
    float acc[4][4] = {};

    for (int k0 = 0; k0 < RR; k0 += 32) {
#pragma unroll
        for (int t = 0; t < 8; t++) {
            int e = tid + t * 256;
            int kk = e >> 6, ii = e & 63;
            As[kk][ii] = Ap[(size_t)(k0 + kk) * CC + i0 + ii];
            Bs[kk][ii] = Bp[(size_t)(k0 + kk) * CC + j0 + ii];
        }
        __syncthreads();
#pragma unroll
        for (int kk = 0; kk < 32; kk++) {
            float a[4], bv[4];
#pragma unroll
            for (int u = 0; u < 4; u++) a[u] = As[kk][ty * 4 + u];
#pragma unroll
            for (int v = 0; v < 4; v++) bv[v] = Bs[kk][tx * 4 + v];
#pragma unroll
            for (int u = 0; u < 4; u++)
#pragma unroll
                for (int v = 0; v < 4; v++)
                    acc[u][v] += a[u] * bv[v];
        }
        __syncthreads();
    }
#pragma unroll
    for (int u = 0; u < 4; u++)
#pragma unroll
        for (int v = 0; v < 4; v++)
            Cp[(size_t)(i0 + ty * 4 + u) * CC + j0 + tx * 4 + v] = acc[u][v];
}

// ---------------------------------------------------------------------------
// Symmetrize: Asym = 0.5*(A + A^T), per batch 256x256
// ---------------------------------------------------------------------------
__global__ void k_sym(const float* __restrict__ A, float* __restrict__ Asym)
{
    int idx = blockIdx.x * 256 + threadIdx.x;
    int b = idx >> 16;
    int rem = idx & 65535;
    int i = rem >> 8, j = rem & 255;
    size_t base = (size_t)b * 65536;
    Asym[base + rem] = 0.5f * (A[base + i * 256 + j] + A[base + j * 256 + i]);
}

// ---------------------------------------------------------------------------
// Build B = M - a*(U + Graw) + a*(M @ Asym),  a = |lr[b]| * s_lr
// NN GEMM over K=256 with fused elementwise epilogue.
// ---------------------------------------------------------------------------
__global__ void k_build_B(const float* __restrict__ M,
                          const float* __restrict__ U,
                          const float* __restrict__ G,
                          const float* __restrict__ Asym,
                          const float* __restrict__ lr,
                          const float* __restrict__ s_lr,
                          float* __restrict__ Bout)
{
    int b = blockIdx.z;
    size_t mb = (size_t)b * RR * CC;
    const float* Mp = M + mb;
    const float* Up = U + mb;
    const float* Gp = G + mb;
    const float* Qp = Asym + (size_t)b * CC * CC;
    float* Bp = Bout + mb;
    float a = fabsf(lr[b]) * s_lr[0];

    int r0 = blockIdx.y * 64, c0 = blockIdx.x * 64;

    __shared__ float Ms[64][33];  // [r][k]
    __shared__ float Qs[32][65];  // [k][c]

    int tid = threadIdx.x;
    int tx = tid & 15, ty = tid >> 4;
    float acc[4][4] = {};

    for (int k0 = 0; k0 < CC; k0 += 32) {
#pragma unroll
        for (int t = 0; t < 8; t++) {
            int e = tid + t * 256;
            int rr = e >> 5, kk = e & 31;
            Ms[rr][kk] = Mp[(size_t)(r0 + rr) * CC + k0 + kk];
            int k2 = e >> 6, cc2 = e & 63;
            Qs[k2][cc2] = Qp[(size_t)(k0 + k2) * CC + c0 + cc2];
        }
        __syncthreads();
#pragma unroll
        for (int kk = 0; kk < 32; kk++) {
            float mv[4], qv[4];
#pragma unroll
            for (int u = 0; u < 4; u++) mv[u] = Ms[ty * 4 + u][kk];
#pragma unroll
            for (int v = 0; v < 4; v++) qv[v] = Qs[kk][tx * 4 + v];
#pragma unroll
            for (int u = 0; u < 4; u++)
#pragma unroll
                for (int v = 0; v < 4; v++)
                    acc[u][v] += mv[u] * qv[v];
        }
        __syncthreads();
    }
#pragma unroll
    for (int u = 0; u < 4; u++)
#pragma unroll
        for (int v = 0; v < 4; v++) {
            size_t off = (size_t)(r0 + ty * 4 + u) * CC + c0 + tx * 4 + v;
            Bp[off] = Mp[off] + a * (acc[u][v] - Up[off] - Gp[off]);
        }
}

// ---------------------------------------------------------------------------
// Per-batch Cholesky (S = L L^T) + in-place triangular inverse of L,
// then write V = R^{-1} = L^{-T} as dense [k][c] (upper triangular).
// One CTA (256 threads) per batch; packed lower triangle in dynamic smem.
// ---------------------------------------------------------------------------
__global__ void k_cholinv(const float* __restrict__ S, float* __restrict__ V)
{
    extern __shared__ float sm[];
    float* Lp = sm;              // packed lower: (i,j) i>=j at i*(i+1)/2 + j
    float* rowbuf = sm + 32896;  // 256-float row buffer

    int b = blockIdx.x;
    int tid = threadIdx.x;
    const float* Sp = S + (size_t)b * 65536;

    // Load lower triangle (packed)
    for (int i = 0; i < 256; i++) {
        if (tid <= i) Lp[i * (i + 1) / 2 + tid] = Sp[(size_t)i * 256 + tid];
    }
    __syncthreads();

    // Right-looking Cholesky, in place
    int i = tid;
    int ibase = i * (i + 1) / 2;
    for (int j = 0; j < 256; j++) {
        int jbase = j * (j + 1) / 2;
        if (tid == 0) Lp[jbase + j] = sqrtf(Lp[jbase + j]);
        __syncthreads();
        float d = Lp[jbase + j];
        float lij = 0.0f;
        if (i > j) {
            lij = Lp[ibase + j] / d;
            Lp[ibase + j] = lij;
        }
        __syncthreads();
        if (i > j) {
            int kbase = (j + 1) * (j + 2) / 2;
            for (int k = j + 1; k <= i; k++) {
                Lp[ibase + k] -= lij * Lp[kbase + j];
                kbase += k + 1;
            }
        }
        __syncthreads();
    }

    // In-place inversion of L (rows ascending):
    // Linv[i2][j] = (delta_ij - sum_{k=j}^{i2-1} L[i2][k]*Linv[k][j]) / L[i2][i2]
    for (int i2 = 0; i2 < 256; i2++) {
        int base = i2 * (i2 + 1) / 2;
        if (tid <= i2) rowbuf[tid] = Lp[base + tid];
        __syncthreads();
        if (tid <= i2) {
            int j = tid;
            float dinv = 1.0f / rowbuf[i2];
            float s = (j == i2) ? 1.0f : 0.0f;
            float accv = 0.0f;
            int kb = j * (j + 1) / 2;
            for (int k = j; k < i2; k++) {
                accv += rowbuf[k] * Lp[kb + j];
                kb += k + 1;
            }
            Lp[base + j] = (s - accv) * dinv;
        }
        __syncthreads();
    }

    // V[k][c] = Linv[c][k] for c >= k, else 0  (dense upper-tri R^{-1})
    float* Vp = V + (size_t)b * 65536;
    for (int idx = tid; idx < 65536; idx += 256) {
        int k = idx >> 8, c = idx & 255;
        float v = 0.0f;
        if (c >= k) v = Lp[c * (c + 1) / 2 + k];
        Vp[idx] = v;
    }
}

// ---------------------------------------------------------------------------
// Output GEMM (transposed write): out[b][c][r] = sum_k B[r][k] * V[k][c]
// ---------------------------------------------------------------------------
__global__ void k_gemm_out(const float* __restrict__ Bm,
                           const float* __restrict__ V,
                           float* __restrict__ Out)
{
    int b = blockIdx.z;
    const float* Bp = Bm + (size_t)b * RR * CC;
    const float* Vp = V + (size_t)b * CC * CC;
    float* Op = Out + (size_t)b * CC * RR;
    int r0 = blockIdx.y * 64, c0 = blockIdx.x * 64;

    __shared__ float Bs[64][33];  // [r][k]
    __shared__ float Vs[32][65];  // [k][c]

    int tid = threadIdx.x;
    int tx = tid & 15, ty = tid >> 4;  // tx -> r, ty -> c
    float acc[4][4] = {};              // [c][r]

    for (int k0 = 0; k0 < CC; k0 += 32) {
#pragma unroll
        for (int t = 0; t < 8; t++) {
            int e = tid + t * 256;
            int rr = e >> 5, kk = e & 31;
            Bs[rr][kk] = Bp[(size_t)(r0 + rr) * CC + k0 + kk];
            int k2 = e >> 6, cc2 = e & 63;
            Vs[k2][cc2] = Vp[(size_t)(k0 + k2) * CC + c0 + cc2];
        }
        __syncthreads();
#pragma unroll
        for (int kk = 0; kk < 32; kk++) {
            float cv[4], rv[4];
#pragma unroll
            for (int u = 0; u < 4; u++) cv[u] = Vs[kk][ty * 4 + u];
#pragma unroll
            for (int v = 0; v < 4; v++) rv[v] = Bs[tx * 4 + v][kk];
#pragma unroll
            for (int u = 0; u < 4; u++)
#pragma unroll
                for (int v = 0; v < 4; v++)
                    acc[u][v] += cv[u] * rv[v];
        }
        __syncthreads();
    }
#pragma unroll
    for (int u = 0; u < 4; u++)
#pragma unroll
        for (int v = 0; v < 4; v++)
            Op[(size_t)(c0 + ty * 4 + u) * RR + r0 + tx * 4 + v] = acc[u][v];
}

// ---------------------------------------------------------------------------
extern "C" void kernel_launch(void* const* d_in, const int* in_sizes, int n_in,
                              void* d_out, int out_size)
{
    const float* M    = (const float*)d_in[0];
    const float* Mg   = (const float*)d_in[1];
    const float* Up   = (const float*)d_in[2];
    const float* lr   = (const float*)d_in[3];
    const float* s_lr = (const float*)d_in[4];
    float* out = (float*)d_out;

    float *gA, *gAsym, *gB, *gV;
    cudaGetSymbolAddress((void**)&gA, g_A);
    cudaGetSymbolAddress((void**)&gAsym, g_Asym);
    cudaGetSymbolAddress((void**)&gB, g_Bm);
    cudaGetSymbolAddress((void**)&gV, g_V);

    cudaFuncSetAttribute(k_cholinv,
                         cudaFuncAttributeMaxDynamicSharedMemorySize, 135168);

    dim3 blk(256);

    // 1) A = M^T Graw
    k_gemm_tn<<<dim3(4, 4, NB), blk>>>(M, Mg, gA);
    // 2) Asym = 0.5*(A + A^T)
    k_sym<<<(NB * 65536) / 256, blk>>>(gA, gAsym);
    // 3) B = M - a*(U + Graw) + a*(M @ Asym)
    k_build_B<<<dim3(4, 36, NB), blk>>>(M, Up, Mg, gAsym, lr, s_lr, gB);
    // 4) S = B^T B
    k_gemm_tn<<<dim3(4, 4, NB), blk>>>(gB, gB, gA);
    // 5) Cholesky + triangular inverse -> V = R^{-1}
    k_cholinv<<<NB, blk, 135168>>>(gA, gV);
    // 6) out[b][c][r] = sum_k B[r][k] V[k][c]
    k_gemm_out<<<dim3(4, 36, NB), blk>>>(gB, gV, out);
}

// round 3
// speedup vs baseline: 1.8377x; 1.8377x over previous
#include <cuda_runtime.h>
#include <cuda_bf16.h>
#include <cstdint>
#include <math.h>

// Batched Stiefel optimizer step via Cholesky-QR.
// Round 3: GEMMs on tensor cores via mma.sync (bf16 split-precision, fp32 acc).
// (tcgen05 unavailable: harness ptxas targets plain sm_103, no 'a' feature.)

#define NB 128
#define RR 2304
#define CC 256

__device__ float g_A[(size_t)NB * CC * CC];     // A = M^T Graw, later S = B^T B
__device__ float g_Asym[(size_t)NB * CC * CC];  // sym(A)
__device__ float g_Bm[(size_t)NB * RR * CC];    // B = M + P
__device__ float g_V[(size_t)NB * CC * CC];     // V = R^{-1} dense upper

// ---------------------------------------------------------------------------
static constexpr int HROWB = 80;     // bytes per smem row (32 bf16 used + pad) -> 20 words, conflict-free frag reads
static constexpr int BUF = 128 * HROWB;              // 10240 B per operand buffer
static constexpr int OFF_AH = 0;
static constexpr int OFF_AL = BUF;
static constexpr int OFF_BH = 2 * BUF;
static constexpr int OFF_BL = 3 * BUF;
static constexpr int STAGE_BYTES = 4 * BUF;          // 40960
static constexpr int GEMM_SMEM = 2 * STAGE_BYTES;    // 81920

__device__ __forceinline__ void mma16816(float* c, const uint32_t* a, const uint32_t* b) {
    asm volatile(
        "mma.sync.aligned.m16n8k16.row.col.f32.bf16.bf16.f32 "
        "{%0,%1,%2,%3}, {%4,%5,%6,%7}, {%8,%9}, {%0,%1,%2,%3};"
        : "+f"(c[0]), "+f"(c[1]), "+f"(c[2]), "+f"(c[3])
        : "r"(a[0]), "r"(a[1]), "r"(a[2]), "r"(a[3]), "r"(b[0]), "r"(b[1]));
}

// split two fp32 into (hi, lo) packed bf16x2
__device__ __forceinline__ void split2(float x0, float x1, uint32_t& h, uint32_t& l) {
    __nv_bfloat16 h0 = __float2bfloat16(x0), h1 = __float2bfloat16(x1);
    float r0 = x0 - __bfloat162float(h0);
    float r1 = x1 - __bfloat162float(h1);
    __nv_bfloat16 l0 = __float2bfloat16(r0), l1 = __float2bfloat16(r1);
    h = ((uint32_t)__bfloat16_as_ushort(h1) << 16) | __bfloat16_as_ushort(h0);
    l = ((uint32_t)__bfloat16_as_ushort(l1) << 16) | __bfloat16_as_ushort(l0);
}

// ---------------------------------------------------------------------------
// Unified GEMM. D[m(128)][n(128)] = sum_k Amma[m][k]*Bmma[n][k], 3-product split.
// MODE 0 (TN, K=KTOT): Amma[m][k]=Ag[k][i0+m], Bmma[n][k]=Bg[k][j0+n];
//          store D -> Op[i0+m][j0+n]           (Op 256x256)
// MODE 2 (NN, K=256):  Amma[m][k]=Ag[i0+m][k], Bmma[n][k]=Bg[k][j0+n];
//          store Op = Ag + a*(D - E1 - E2)     (B-build; Ag == M, Op 2304x256)
// MODE 3 (NN, K=256):  same operands; store Op[j0+n][i0+m] = D (transposed)
// ---------------------------------------------------------------------------
template <int MODE, int KTOT>
__global__ void __launch_bounds__(256)
k_gemm(const float* __restrict__ Ag_, const float* __restrict__ Bg_,
       const float* __restrict__ E1_, const float* __restrict__ E2_,
       const float* __restrict__ lr, const float* __restrict__ s_lr,
       float* __restrict__ Out)
{
    extern __shared__ char dsm[];
    const int tid = threadIdx.x;
    const int lane = tid & 31, warp = tid >> 5;
    const int wm = warp & 3, wn = warp >> 2;    // warp tile: rows wm*32, cols wn*64
    const int g = lane >> 2, tg = lane & 3;
    const int b = blockIdx.z;
    const int j0 = blockIdx.x * 128;
    const int i0 = blockIdx.y * 128;

    const size_t bigS = (size_t)RR * CC, smlS = (size_t)CC * CC;
    const float* Ag = Ag_ + (size_t)b * bigS;
    const float* Bg = Bg_ + (size_t)b * ((MODE == 0) ? bigS : smlS);
    float* Op = Out + (size_t)b * ((MODE == 0) ? smlS : bigS);

    float acc[2][8][4] = {};
    float ra[16], rb[16];

    constexpr int NC = KTOT / 32;

    // ---- load chunk c into registers ----
    auto LOADR = [&](int c) {
        const int k0 = c * 32;
        if (MODE == 0) {
#pragma unroll
            for (int it = 0; it < 4; ++it) {
                int idx = tid + it * 256;
                int m = idx & 127, kq = idx >> 7;
#pragma unroll
                for (int j = 0; j < 4; ++j)
                    ra[it * 4 + j] = Ag[(size_t)(k0 + kq * 4 + j) * CC + i0 + m];
            }
        } else {
#pragma unroll
            for (int it = 0; it < 4; ++it) {
                int idx = tid + it * 256;
                int kq = idx & 7, m = idx >> 3;
                float4 v = *(const float4*)(Ag + (size_t)(i0 + m) * CC + k0 + kq * 4);
                ra[it * 4 + 0] = v.x; ra[it * 4 + 1] = v.y;
                ra[it * 4 + 2] = v.z; ra[it * 4 + 3] = v.w;
            }
        }
#pragma unroll
        for (int it = 0; it < 4; ++it) {
            int idx = tid + it * 256;
            int n = idx & 127, kq = idx >> 7;
#pragma unroll
            for (int j = 0; j < 4; ++j)
                rb[it * 4 + j] = Bg[(size_t)(k0 + kq * 4 + j) * CC + j0 + n];
        }
    };

    // ---- split regs and store to smem stage s ----
    auto STORER = [&](int s) {
        char* st = dsm + s * STAGE_BYTES;
#pragma unroll
        for (int it = 0; it < 4; ++it) {
            int idx = tid + it * 256;
            int m, kq;
            if (MODE == 0) { m = idx & 127; kq = idx >> 7; }
            else           { kq = idx & 7;  m = idx >> 3; }
            uint32_t h01, l01, h23, l23;
            split2(ra[it * 4 + 0], ra[it * 4 + 1], h01, l01);
            split2(ra[it * 4 + 2], ra[it * 4 + 3], h23, l23);
            *(uint2*)(st + OFF_AH + m * HROWB + kq * 8) = make_uint2(h01, h23);
            *(uint2*)(st + OFF_AL + m * HROWB + kq * 8) = make_uint2(l01, l23);
        }
#pragma unroll
        for (int it = 0; it < 4; ++it) {
            int idx = tid + it * 256;
            int n = idx & 127, kq = idx >> 7;
            uint32_t h01, l01, h23, l23;
            split2(rb[it * 4 + 0], rb[it * 4 + 1], h01, l01);
            split2(rb[it * 4 + 2], rb[it * 4 + 3], h23, l23);
            *(uint2*)(st + OFF_BH + n * HROWB + kq * 8) = make_uint2(h01, h23);
            *(uint2*)(st + OFF_BL + n * HROWB + kq * 8) = make_uint2(l01, l23);
        }
    };

    // ---- consume stage s: acc += Ah*Bh + Al*Bh + Ah*Bl ----
    auto COMPUTE = [&](int s) {
        const char* st = dsm + s * STAGE_BYTES;
#pragma unroll
        for (int ks = 0; ks < 32; ks += 16) {
            uint32_t ah[2][4], al[2][4], bb[8][2];
#pragma unroll
            for (int mi = 0; mi < 2; ++mi) {
                const char* pa = st + (wm * 32 + mi * 16 + g) * HROWB + ks * 2 + tg * 4;
                ah[mi][0] = *(const uint32_t*)(pa + OFF_AH);
                ah[mi][1] = *(const uint32_t*)(pa + OFF_AH + 8 * HROWB);
                ah[mi][2] = *(const uint32_t*)(pa + OFF_AH + 16);
                ah[mi][3] = *(const uint32_t*)(pa + OFF_AH + 8 * HROWB + 16);
                al[mi][0] = *(const uint32_t*)(pa + OFF_AL);
                al[mi][1] = *(const uint32_t*)(pa + OFF_AL + 8 * HROWB);
                al[mi][2] = *(const uint32_t*)(pa + OFF_AL + 16);
                al[mi][3] = *(const uint32_t*)(pa + OFF_AL + 8 * HROWB + 16);
            }
#pragma unroll
            for (int ni = 0; ni < 8; ++ni) {
                const char* pb = st + OFF_BH + (wn * 64 + ni * 8 + g) * HROWB + ks * 2 + tg * 4;
                bb[ni][0] = *(const uint32_t*)pb;
                bb[ni][1] = *(const uint32_t*)(pb + 16);
            }
#pragma unroll
            for (int mi = 0; mi < 2; ++mi)
#pragma unroll
                for (int ni = 0; ni < 8; ++ni) {
                    mma16816(acc[mi][ni], ah[mi], bb[ni]);
                    mma16816(acc[mi][ni], al[mi], bb[ni]);
                }
#pragma unroll
            for (int ni = 0; ni < 8; ++ni) {
                const char* pb = st + OFF_BL + (wn * 64 + ni * 8 + g) * HROWB + ks * 2 + tg * 4;
                bb[ni][0] = *(const uint32_t*)pb;
                bb[ni][1] = *(const uint32_t*)(pb + 16);
            }
#pragma unroll
            for (int mi = 0; mi < 2; ++mi)
#pragma unroll
                for (int ni = 0; ni < 8; ++ni)
                    mma16816(acc[mi][ni], ah[mi], bb[ni]);
        }
    };

    // ---- pipeline ----
    LOADR(0);
    STORER(0);
    __syncthreads();
    for (int c = 0; c < NC; ++c) {
        if (c + 1 < NC) LOADR(c + 1);
        COMPUTE(c & 1);
        if (c + 1 < NC) STORER((c + 1) & 1);
        __syncthreads();
    }

    // ---- epilogue ----
    if (MODE == 0) {
#pragma unroll
        for (int mi = 0; mi < 2; ++mi)
#pragma unroll
            for (int ni = 0; ni < 8; ++ni) {
                int row = i0 + wm * 32 + mi * 16 + g;
                int col = j0 + wn * 64 + ni * 8 + tg * 2;
                *(float2*)(Op + (size_t)row * CC + col) =
                    make_float2(acc[mi][ni][0], acc[mi][ni][1]);
                *(float2*)(Op + (size_t)(row + 8) * CC + col) =
                    make_float2(acc[mi][ni][2], acc[mi][ni][3]);
            }
    } else if (MODE == 2) {
        const float aSc = fabsf(lr[b]) * s_lr[0];
        const float* E1 = E1_ + (size_t)b * bigS;
        const float* E2 = E2_ + (size_t)b * bigS;
#pragma unroll
        for (int mi = 0; mi < 2; ++mi)
#pragma unroll
            for (int ni = 0; ni < 8; ++ni) {
                int row = i0 + wm * 32 + mi * 16 + g;
                int col = j0 + wn * 64 + ni * 8 + tg * 2;
#pragma unroll
                for (int h = 0; h < 2; ++h) {
                    size_t o = (size_t)(row + 8 * h) * CC + col;
                    float2 mv = *(const float2*)(Ag + o);
                    float2 uv = *(const float2*)(E1 + o);
                    float2 gv = *(const float2*)(E2 + o);
                    float2 r;
                    r.x = mv.x + aSc * (acc[mi][ni][2 * h + 0] - uv.x - gv.x);
                    r.y = mv.y + aSc * (acc[mi][ni][2 * h + 1] - uv.y - gv.y);
                    *(float2*)(Op + o) = r;
                }
            }
    } else {
        // MODE 3: transpose via smem, then coalesced writes
        const int TP = 132;
        float* T = (float*)dsm;
#pragma unroll
        for (int mi = 0; mi < 2; ++mi)
#pragma unroll
            for (int ni = 0; ni < 8; ++ni) {
                int ml = wm * 32 + mi * 16 + g;
                int nl = wn * 64 + ni * 8 + tg * 2;
                T[nl * TP + ml]           = acc[mi][ni][0];
                T[(nl + 1) * TP + ml]     = acc[mi][ni][1];
                T[nl * TP + ml + 8]       = acc[mi][ni][2];
                T[(nl + 1) * TP + ml + 8] = acc[mi][ni][3];
            }
        __syncthreads();
        int n = tid >> 1, sh = (tid & 1) * 64;
        const float* src = T + n * TP + sh;
        float* dst = Op + (size_t)(j0 + n) * RR + i0 + sh;
#pragma unroll
        for (int q = 0; q < 16; ++q)
            *(float4*)(dst + q * 4) = *(const float4*)(src + q * 4);
    }
}

// ---------------------------------------------------------------------------
// Symmetrize: Asym = 0.5*(A + A^T)
// ---------------------------------------------------------------------------
__global__ void k_sym(const float* __restrict__ A, float* __restrict__ Asym) {
    int idx = blockIdx.x * 256 + threadIdx.x;
    int b = idx >> 16;
    int rem = idx & 65535;
    int i = rem >> 8, j = rem & 255;
    size_t base = (size_t)b * 65536;
    Asym[base + rem] = 0.5f * (A[base + i * 256 + j] + A[base + j * 256 + i]);
}

// ---------------------------------------------------------------------------
// Per-batch Cholesky + triangular inverse -> V = R^{-1} (dense upper)
// ---------------------------------------------------------------------------
__global__ void k_cholinv(const float* __restrict__ S, float* __restrict__ V) {
    extern __shared__ float sm[];
    float* Lp = sm;
    float* rowbuf = sm + 32896;

    int b = blockIdx.x;
    int tid = threadIdx.x;
    const float* Sp = S + (size_t)b * 65536;

    for (int i = 0; i < 256; i++)
        if (tid <= i) Lp[i * (i + 1) / 2 + tid] = Sp[(size_t)i * 256 + tid];
    __syncthreads();

    int i = tid;
    int ibase = i * (i + 1) / 2;
    for (int j = 0; j < 256; j++) {
        int jbase = j * (j + 1) / 2;
        if (tid == 0) Lp[jbase + j] = sqrtf(Lp[jbase + j]);
        __syncthreads();
        float d = Lp[jbase + j];
        float lij = 0.0f;
        if (i > j) { lij = Lp[ibase + j] / d; Lp[ibase + j] = lij; }
        __syncthreads();
        if (i > j) {
            int kbase = (j + 1) * (j + 2) / 2;
            for (int k = j + 1; k <= i; k++) {
                Lp[ibase + k] -= lij * Lp[kbase + j];
                kbase += k + 1;
            }
        }
        __syncthreads();
    }

    for (int i2 = 0; i2 < 256; i2++) {
        int base = i2 * (i2 + 1) / 2;
        if (tid <= i2) rowbuf[tid] = Lp[base + tid];
        __syncthreads();
        if (tid <= i2) {
            int j = tid;
            float dinv = 1.0f / rowbuf[i2];
            float s = (j == i2) ? 1.0f : 0.0f;
            float accv = 0.0f;
            int kb = j * (j + 1) / 2;
            for (int k = j; k < i2; k++) {
                accv += rowbuf[k] * Lp[kb + j];
                kb += k + 1;
            }
            Lp[base + j] = (s - accv) * dinv;
        }
        __syncthreads();
    }

    float* Vp = V + (size_t)b * 65536;
    for (int idx = tid; idx < 65536; idx += 256) {
        int k = idx >> 8, c = idx & 255;
        float v = 0.0f;
        if (c >= k) v = Lp[c * (c + 1) / 2 + k];
        Vp[idx] = v;
    }
}

// ---------------------------------------------------------------------------
extern "C" void kernel_launch(void* const* d_in, const int* in_sizes, int n_in,
                              void* d_out, int out_size)
{
    const float* M    = (const float*)d_in[0];
    const float* Mg   = (const float*)d_in[1];
    const float* Up   = (const float*)d_in[2];
    const float* lr   = (const float*)d_in[3];
    const float* s_lr = (const float*)d_in[4];
    float* out = (float*)d_out;

    float *gA, *gAsym, *gB, *gV;
    cudaGetSymbolAddress((void**)&gA, g_A);
    cudaGetSymbolAddress((void**)&gAsym, g_Asym);
    cudaGetSymbolAddress((void**)&gB, g_Bm);
    cudaGetSymbolAddress((void**)&gV, g_V);

    cudaFuncSetAttribute(k_cholinv, cudaFuncAttributeMaxDynamicSharedMemorySize, 135168);
    cudaFuncSetAttribute(k_gemm<0, RR>, cudaFuncAttributeMaxDynamicSharedMemorySize, GEMM_SMEM);
    cudaFuncSetAttribute(k_gemm<2, CC>, cudaFuncAttributeMaxDynamicSharedMemorySize, GEMM_SMEM);
    cudaFuncSetAttribute(k_gemm<3, CC>, cudaFuncAttributeMaxDynamicSharedMemorySize, GEMM_SMEM);

    dim3 blk(256);

    // 1) A = M^T Graw
    k_gemm<0, RR><<<dim3(2, 2, NB), blk, GEMM_SMEM>>>(M, Mg, nullptr, nullptr, lr, s_lr, gA);
    // 2) Asym = 0.5*(A + A^T)
    k_sym<<<(NB * 65536) / 256, blk>>>(gA, gAsym);
    // 3) B = M + a*(M@Asym - U - Graw)
    k_gemm<2, CC><<<dim3(2, 18, NB), blk, GEMM_SMEM>>>(M, gAsym, Up, Mg, lr, s_lr, gB);
    // 4) S = B^T B
    k_gemm<0, RR><<<dim3(2, 2, NB), blk, GEMM_SMEM>>>(gB, gB, nullptr, nullptr, lr, s_lr, gA);
    // 5) Cholesky + triangular inverse -> V = R^{-1}
    k_cholinv<<<NB, blk, 135168>>>(gA, gV);
    // 6) out[b][c][r] = sum_k B[r][k] V[k][c]
    k_gemm<3, CC><<<dim3(2, 18, NB), blk, GEMM_SMEM>>>(gB, gV, nullptr, nullptr, lr, s_lr, out);
}

// round 5
// speedup vs baseline: 2.7525x; 1.4978x over previous
#include <cuda_runtime.h>
#include <cuda_bf16.h>
#include <cstdint>
#include <math.h>

// Batched Stiefel optimizer step via Cholesky-QR.
// Round 5: fix B2 packed-triangular read bug (K==J diag-inverse block must be
// read with a (k>=c) guard — packed storage has no zeros above the diagonal).

#define NB 128
#define RR 2304
#define CC 256

__device__ float g_A[(size_t)NB * CC * CC];     // A = M^T Graw, later S = B^T B
__device__ float g_Asym[(size_t)NB * CC * CC];  // sym(A)
__device__ float g_Bm[(size_t)NB * RR * CC];    // B = M + P
__device__ float g_V[(size_t)NB * CC * CC];     // V = R^{-1} dense upper

// ---------------------------------------------------------------------------
static constexpr int HROWB = 80;                 // smem row bytes (conflict-free frags)
static constexpr int BUF = 128 * HROWB;
static constexpr int OFF_AH = 0;
static constexpr int OFF_AL = BUF;
static constexpr int OFF_BH = 2 * BUF;
static constexpr int OFF_BL = 3 * BUF;
static constexpr int STAGE_BYTES = 4 * BUF;      // 40960
static constexpr int GEMM_SMEM = 2 * STAGE_BYTES;

__device__ __forceinline__ void mma16816(float* c, const uint32_t* a, const uint32_t* b) {
    asm volatile(
        "mma.sync.aligned.m16n8k16.row.col.f32.bf16.bf16.f32 "
        "{%0,%1,%2,%3}, {%4,%5,%6,%7}, {%8,%9}, {%0,%1,%2,%3};"
        : "+f"(c[0]), "+f"(c[1]), "+f"(c[2]), "+f"(c[3])
        : "r"(a[0]), "r"(a[1]), "r"(a[2]), "r"(a[3]), "r"(b[0]), "r"(b[1]));
}

__device__ __forceinline__ void split2(float x0, float x1, uint32_t& h, uint32_t& l) {
    __nv_bfloat16 h0 = __float2bfloat16(x0), h1 = __float2bfloat16(x1);
    float r0 = x0 - __bfloat162float(h0);
    float r1 = x1 - __bfloat162float(h1);
    __nv_bfloat16 l0 = __float2bfloat16(r0), l1 = __float2bfloat16(r1);
    h = ((uint32_t)__bfloat16_as_ushort(h1) << 16) | __bfloat16_as_ushort(h0);
    l = ((uint32_t)__bfloat16_as_ushort(l1) << 16) | __bfloat16_as_ushort(l0);
}

// ---------------------------------------------------------------------------
// Unified GEMM. 128x128 CTA tile, split-bf16 3-product, mma.sync.
// ---------------------------------------------------------------------------
template <int MODE, int KTOT>
__global__ void __launch_bounds__(256, 2)
k_gemm(const float* __restrict__ Ag_, const float* __restrict__ Bg_,
       const float* __restrict__ E1_, const float* __restrict__ E2_,
       const float* __restrict__ lr, const float* __restrict__ s_lr,
       float* __restrict__ Out)
{
    extern __shared__ char dsm[];
    const int tid = threadIdx.x;
    const int lane = tid & 31, warp = tid >> 5;
    const int wm = warp & 3, wn = warp >> 2;
    const int g = lane >> 2, tg = lane & 3;
    const int b = blockIdx.z;
    const int j0 = blockIdx.x * 128;
    const int i0 = blockIdx.y * 128;

    const size_t bigS = (size_t)RR * CC, smlS = (size_t)CC * CC;
    const float* Ag = Ag_ + (size_t)b * bigS;
    const float* Bg = Bg_ + (size_t)b * ((MODE == 0) ? bigS : smlS);
    float* Op = Out + (size_t)b * ((MODE == 0) ? smlS : bigS);

    float acc[2][8][4] = {};
    float ra[16], rb[16];

    constexpr int NC = KTOT / 32;

    auto LOADR = [&](int c) {
        const int k0 = c * 32;
        if (MODE == 0) {
#pragma unroll
            for (int it = 0; it < 4; ++it) {
                int idx = tid + it * 256;
                int m = idx & 127, kq = idx >> 7;
#pragma unroll
                for (int j = 0; j < 4; ++j)
                    ra[it * 4 + j] = Ag[(size_t)(k0 + kq * 4 + j) * CC + i0 + m];
            }
        } else {
#pragma unroll
            for (int it = 0; it < 4; ++it) {
                int idx = tid + it * 256;
                int kq = idx & 7, m = idx >> 3;
                float4 v = *(const float4*)(Ag + (size_t)(i0 + m) * CC + k0 + kq * 4);
                ra[it * 4 + 0] = v.x; ra[it * 4 + 1] = v.y;
                ra[it * 4 + 2] = v.z; ra[it * 4 + 3] = v.w;
            }
        }
#pragma unroll
        for (int it = 0; it < 4; ++it) {
            int idx = tid + it * 256;
            int n = idx & 127, kq = idx >> 7;
#pragma unroll
            for (int j = 0; j < 4; ++j)
                rb[it * 4 + j] = Bg[(size_t)(k0 + kq * 4 + j) * CC + j0 + n];
        }
    };

    auto STORER = [&](int s) {
        char* st = dsm + s * STAGE_BYTES;
#pragma unroll
        for (int it = 0; it < 4; ++it) {
            int idx = tid + it * 256;
            int m, kq;
            if (MODE == 0) { m = idx & 127; kq = idx >> 7; }
            else           { kq = idx & 7;  m = idx >> 3; }
            uint32_t h01, l01, h23, l23;
            split2(ra[it * 4 + 0], ra[it * 4 + 1], h01, l01);
            split2(ra[it * 4 + 2], ra[it * 4 + 3], h23, l23);
            *(uint2*)(st + OFF_AH + m * HROWB + kq * 8) = make_uint2(h01, h23);
            *(uint2*)(st + OFF_AL + m * HROWB + kq * 8) = make_uint2(l01, l23);
        }
#pragma unroll
        for (int it = 0; it < 4; ++it) {
            int idx = tid + it * 256;
            int n = idx & 127, kq = idx >> 7;
            uint32_t h01, l01, h23, l23;
            split2(rb[it * 4 + 0], rb[it * 4 + 1], h01, l01);
            split2(rb[it * 4 + 2], rb[it * 4 + 3], h23, l23);
            *(uint2*)(st + OFF_BH + n * HROWB + kq * 8) = make_uint2(h01, h23);
            *(uint2*)(st + OFF_BL + n * HROWB + kq * 8) = make_uint2(l01, l23);
        }
    };

    auto COMPUTE = [&](int s) {
        const char* st = dsm + s * STAGE_BYTES;
#pragma unroll
        for (int ks = 0; ks < 32; ks += 16) {
            uint32_t ah[2][4], al[2][4], bb[8][2];
#pragma unroll
            for (int mi = 0; mi < 2; ++mi) {
                const char* pa = st + (wm * 32 + mi * 16 + g) * HROWB + ks * 2 + tg * 4;
                ah[mi][0] = *(const uint32_t*)(pa + OFF_AH);
                ah[mi][1] = *(const uint32_t*)(pa + OFF_AH + 8 * HROWB);
                ah[mi][2] = *(const uint32_t*)(pa + OFF_AH + 16);
                ah[mi][3] = *(const uint32_t*)(pa + OFF_AH + 8 * HROWB + 16);
                al[mi][0] = *(const uint32_t*)(pa + OFF_AL);
                al[mi][1] = *(const uint32_t*)(pa + OFF_AL + 8 * HROWB);
                al[mi][2] = *(const uint32_t*)(pa + OFF_AL + 16);
                al[mi][3] = *(const uint32_t*)(pa + OFF_AL + 8 * HROWB + 16);
            }
#pragma unroll
            for (int ni = 0; ni < 8; ++ni) {
                const char* pb = st + OFF_BH + (wn * 64 + ni * 8 + g) * HROWB + ks * 2 + tg * 4;
                bb[ni][0] = *(const uint32_t*)pb;
                bb[ni][1] = *(const uint32_t*)(pb + 16);
            }
#pragma unroll
            for (int mi = 0; mi < 2; ++mi)
#pragma unroll
                for (int ni = 0; ni < 8; ++ni) {
                    mma16816(acc[mi][ni], ah[mi], bb[ni]);
                    mma16816(acc[mi][ni], al[mi], bb[ni]);
                }
#pragma unroll
            for (int ni = 0; ni < 8; ++ni) {
                const char* pb = st + OFF_BL + (wn * 64 + ni * 8 + g) * HROWB + ks * 2 + tg * 4;
                bb[ni][0] = *(const uint32_t*)pb;
                bb[ni][1] = *(const uint32_t*)(pb + 16);
            }
#pragma unroll
            for (int mi = 0; mi < 2; ++mi)
#pragma unroll
                for (int ni = 0; ni < 8; ++ni)
                    mma16816(acc[mi][ni], ah[mi], bb[ni]);
        }
    };

    LOADR(0);
    STORER(0);
    __syncthreads();
    for (int c = 0; c < NC; ++c) {
        if (c + 1 < NC) LOADR(c + 1);
        COMPUTE(c & 1);
        if (c + 1 < NC) STORER((c + 1) & 1);
        __syncthreads();
    }

    if (MODE == 0) {
#pragma unroll
        for (int mi = 0; mi < 2; ++mi)
#pragma unroll
            for (int ni = 0; ni < 8; ++ni) {
                int row = i0 + wm * 32 + mi * 16 + g;
                int col = j0 + wn * 64 + ni * 8 + tg * 2;
                *(float2*)(Op + (size_t)row * CC + col) =
                    make_float2(acc[mi][ni][0], acc[mi][ni][1]);
                *(float2*)(Op + (size_t)(row + 8) * CC + col) =
                    make_float2(acc[mi][ni][2], acc[mi][ni][3]);
            }
    } else if (MODE == 2) {
        const float aSc = fabsf(lr[b]) * s_lr[0];
        const float* E1 = E1_ + (size_t)b * bigS;
        const float* E2 = E2_ + (size_t)b * bigS;
#pragma unroll
        for (int mi = 0; mi < 2; ++mi)
#pragma unroll
            for (int ni = 0; ni < 8; ++ni) {
                int row = i0 + wm * 32 + mi * 16 + g;
                int col = j0 + wn * 64 + ni * 8 + tg * 2;
#pragma unroll
                for (int h = 0; h < 2; ++h) {
                    size_t o = (size_t)(row + 8 * h) * CC + col;
                    float2 mv = *(const float2*)(Ag + o);
                    float2 uv = *(const float2*)(E1 + o);
                    float2 gv = *(const float2*)(E2 + o);
                    float2 r;
                    r.x = mv.x + aSc * (acc[mi][ni][2 * h + 0] - uv.x - gv.x);
                    r.y = mv.y + aSc * (acc[mi][ni][2 * h + 1] - uv.y - gv.y);
                    *(float2*)(Op + o) = r;
                }
            }
    } else {
        const int TP = 132;
        float* T = (float*)dsm;
#pragma unroll
        for (int mi = 0; mi < 2; ++mi)
#pragma unroll
            for (int ni = 0; ni < 8; ++ni) {
                int ml = wm * 32 + mi * 16 + g;
                int nl = wn * 64 + ni * 8 + tg * 2;
                T[nl * TP + ml]           = acc[mi][ni][0];
                T[(nl + 1) * TP + ml]     = acc[mi][ni][1];
                T[nl * TP + ml + 8]       = acc[mi][ni][2];
                T[(nl + 1) * TP + ml + 8] = acc[mi][ni][3];
            }
        __syncthreads();
        int n = tid >> 1, sh = (tid & 1) * 64;
        const float* src = T + n * TP + sh;
        float* dst = Op + (size_t)(j0 + n) * RR + i0 + sh;
#pragma unroll
        for (int q = 0; q < 16; ++q)
            *(float4*)(dst + q * 4) = *(const float4*)(src + q * 4);
    }
}

// ---------------------------------------------------------------------------
__global__ void k_sym(const float* __restrict__ A, float* __restrict__ Asym) {
    int idx = blockIdx.x * 256 + threadIdx.x;
    int b = idx >> 16;
    int rem = idx & 65535;
    int i = rem >> 8, j = rem & 255;
    size_t base = (size_t)b * 65536;
    Asym[base + rem] = 0.5f * (A[base + i * 256 + j] + A[base + j * 256 + i]);
}

// ---------------------------------------------------------------------------
// Blocked Cholesky (panel=32) + blocked triangular inverse, packed lower
// storage in smem. One CTA (256 thr) per batch. Then V = L^{-T} dense upper.
// ---------------------------------------------------------------------------
__device__ __forceinline__ int tri(int r) { return (r * (r + 1)) >> 1; }

static constexpr int CHOL_SMEM = (32896 + 8704) * 4;  // Lp + P = 166400 B

__global__ void __launch_bounds__(256, 1)
k_cholinv(const float* __restrict__ S, float* __restrict__ V)
{
    extern __shared__ float sm[];
    float* Lp = sm;          // packed lower, 32896 floats
    float* P  = sm + 32896;  // panel buffer (pitch 34) / scratch, 8704 floats

    const int b = blockIdx.x;
    const int tid = threadIdx.x;
    const float* Sp = S + (size_t)b * 65536;

    for (int i = 0; i < 256; i++)
        if (tid <= i) Lp[tri(i) + tid] = Sp[(size_t)i * 256 + tid];
    __syncthreads();

    // ===================== Phase A: blocked Cholesky ======================
    for (int p = 0; p < 8; ++p) {
        const int c0 = 32 * p, rows = 256 - c0;

        // 1) copy panel into dense P (pitch 34)
        for (int idx = tid; idx < rows * 32; idx += 256) {
            int lr = idx >> 5, c = idx & 31;
            int r = c0 + lr, gc = c0 + c;
            P[lr * 34 + c] = (gc <= r) ? Lp[tri(r) + gc] : 0.0f;
        }
        __syncthreads();

        // 2) factor 32x32 diagonal block
        for (int j = 0; j < 32; ++j) {
            if (tid == 0) P[j * 34 + j] = sqrtf(P[j * 34 + j]);
            __syncthreads();
            if (tid < 32 && tid > j) P[tid * 34 + j] /= P[j * 34 + j];
            __syncthreads();
            if (tid < 32 && tid > j) {
                float lij = P[tid * 34 + j];
                for (int k = j + 1; k <= tid; ++k)
                    P[tid * 34 + k] -= lij * P[k * 34 + j];
            }
            __syncthreads();
        }

        // 3) TRSM rows (one row per thread)
        {
            int nr = rows - 32;
            if (tid < nr) {
                int lr = 32 + tid;
                float x[32];
#pragma unroll
                for (int c = 0; c < 32; ++c) x[c] = P[lr * 34 + c];
#pragma unroll
                for (int j = 0; j < 32; ++j) {
                    float s = x[j];
#pragma unroll
                    for (int k = 0; k < j; ++k) s -= x[k] * P[j * 34 + k];
                    x[j] = s / P[j * 34 + j];
                }
                int rb = tri(c0 + lr) + c0;
#pragma unroll
                for (int c = 0; c < 32; ++c) { P[lr * 34 + c] = x[c]; Lp[rb + c] = x[c]; }
            }
            if (tid < 32) {
                int rb = tri(c0 + tid) + c0;
                for (int c = 0; c <= tid; ++c) Lp[rb + c] = P[tid * 34 + c];
            }
        }
        __syncthreads();

        // 4) SYRK trailing update (2x2 register-blocked tasks)
        int T = rows - 32;
        if (T > 0) {
            int Tb = T >> 1;
            int ntask = (Tb * (Tb + 1)) >> 1;
            for (int t = tid; t < ntask; t += 256) {
                int bi = (int)((sqrtf(8.0f * (float)t + 1.0f) - 1.0f) * 0.5f);
                while (((bi + 1) * (bi + 2)) / 2 <= t) ++bi;
                while ((bi * (bi + 1)) / 2 > t) --bi;
                int bj = t - (bi * (bi + 1)) / 2;
                int i0 = 32 + 2 * bi, j0 = 32 + 2 * bj;
                const float* Pi0 = P + i0 * 34;
                const float* Pi1 = Pi0 + 34;
                const float* Pj0 = P + j0 * 34;
                const float* Pj1 = Pj0 + 34;
                float a00 = 0, a01 = 0, a10 = 0, a11 = 0;
#pragma unroll
                for (int q = 0; q < 32; q += 2) {
                    float2 vi0 = *(const float2*)(Pi0 + q), vi1 = *(const float2*)(Pi1 + q);
                    float2 vj0 = *(const float2*)(Pj0 + q), vj1 = *(const float2*)(Pj1 + q);
                    a00 += vi0.x * vj0.x + vi0.y * vj0.y;
                    a01 += vi0.x * vj1.x + vi0.y * vj1.y;
                    a10 += vi1.x * vj0.x + vi1.y * vj0.y;
                    a11 += vi1.x * vj1.x + vi1.y * vj1.y;
                }
                int gr0 = c0 + i0, gr1 = gr0 + 1, gc0 = c0 + j0, gc1 = gc0 + 1;
                int rb0 = tri(gr0), rb1 = tri(gr1);
                Lp[rb0 + gc0] -= a00;
                if (bj < bi) Lp[rb0 + gc1] -= a01;
                Lp[rb1 + gc0] -= a10;
                Lp[rb1 + gc1] -= a11;
            }
        }
        __syncthreads();
    }

    // ============ Phase B: W = L^{-1} (blocked, in place in Lp) ===========
    // B1: invert 8 diagonal 32x32 blocks; warp w -> block w, lane = column.
    {
        int w = tid >> 5, j = tid & 31;
        int g0 = 32 * w;
        float wc[32];
#pragma unroll
        for (int i = 0; i < 32; ++i) {
            int rb = tri(g0 + i) + g0;
            float acc = 0.0f;
#pragma unroll
            for (int k = 0; k < i; ++k) acc += Lp[rb + k] * wc[k];
            wc[i] = (((i == j) ? 1.0f : 0.0f) - acc) / Lp[rb + i];
        }
        __syncthreads();
#pragma unroll
        for (int i = 0; i < 32; ++i)
            if (i >= j) Lp[tri(g0 + i) + g0 + j] = wc[i];
    }
    __syncthreads();

    // B2: off-diagonal blocks. W[I][J] = -Winv[I][I] * sum_{K=J}^{I-1} L[I][K] W[K][J]
    {
        int ti = tid >> 4, tj = tid & 15;
        int r0 = 2 * ti, r1 = r0 + 1, cA = 2 * tj, cB = cA + 1;
        for (int J = 0; J < 8; ++J) {
            for (int I = J + 1; I < 8; ++I) {
                int lb0 = tri(32 * I + r0), lb1 = tri(32 * I + r1);
                float a00 = 0, a01 = 0, a10 = 0, a11 = 0;
                // K = J: W[J][J] is the diag inverse, stored packed-TRIANGULAR.
                // Entries above its diagonal are structural zeros NOT present in
                // packed storage -> guard with (k >= c).
                {
                    int la0 = lb0 + 32 * J, la1 = lb1 + 32 * J;
#pragma unroll 8
                    for (int k = 0; k < 32; ++k) {
                        float x0 = Lp[la0 + k], x1 = Lp[la1 + k];
                        int wb = tri(32 * J + k) + 32 * J;
                        float y0 = (k >= cA) ? Lp[wb + cA] : 0.0f;
                        float y1 = (k >= cB) ? Lp[wb + cB] : 0.0f;
                        a00 += x0 * y0; a01 += x0 * y1;
                        a10 += x1 * y0; a11 += x1 * y1;
                    }
                }
                // K = J+1 .. I-1: W[K][J] blocks are dense (full 32x32 writes)
                for (int K = J + 1; K < I; ++K) {
                    int la0 = lb0 + 32 * K, la1 = lb1 + 32 * K;
#pragma unroll 8
                    for (int k = 0; k < 32; ++k) {
                        float x0 = Lp[la0 + k], x1 = Lp[la1 + k];
                        int wb = tri(32 * K + k) + 32 * J;
                        float y0 = Lp[wb + cA], y1 = Lp[wb + cB];
                        a00 += x0 * y0; a01 += x0 * y1;
                        a10 += x1 * y0; a11 += x1 * y1;
                    }
                }
                P[r0 * 33 + cA] = a00; P[r0 * 33 + cB] = a01;
                P[r1 * 33 + cA] = a10; P[r1 * 33 + cB] = a11;
                __syncthreads();
                float b00 = 0, b01 = 0, b10 = 0, b11 = 0;
                int db0 = lb0 + 32 * I, db1 = lb1 + 32 * I;
                for (int k = 0; k <= r1; ++k) {
                    float w0 = (k <= r0) ? Lp[db0 + k] : 0.0f;
                    float w1 = Lp[db1 + k];
                    float t0 = P[k * 33 + cA], t1 = P[k * 33 + cB];
                    b00 += w0 * t0; b01 += w0 * t1;
                    b10 += w1 * t0; b11 += w1 * t1;
                }
                __syncthreads();
                Lp[lb0 + 32 * J + cA] = -b00; Lp[lb0 + 32 * J + cB] = -b01;
                Lp[lb1 + 32 * J + cA] = -b10; Lp[lb1 + 32 * J + cB] = -b11;
                __syncthreads();
            }
        }
    }

    // V[k][c] = W[c][k] for c >= k (dense upper R^{-1}), else 0
    float* Vp = V + (size_t)b * 65536;
    for (int idx = tid; idx < 65536; idx += 256) {
        int k = idx >> 8, c = idx & 255;
        Vp[idx] = (c >= k) ? Lp[tri(c) + k] : 0.0f;
    }
}

// ---------------------------------------------------------------------------
extern "C" void kernel_launch(void* const* d_in, const int* in_sizes, int n_in,
                              void* d_out, int out_size)
{
    const float* M    = (const float*)d_in[0];
    const float* Mg   = (const float*)d_in[1];
    const float* Up   = (const float*)d_in[2];
    const float* lr   = (const float*)d_in[3];
    const float* s_lr = (const float*)d_in[4];
    float* out = (float*)d_out;

    float *gA, *gAsym, *gB, *gV;
    cudaGetSymbolAddress((void**)&gA, g_A);
    cudaGetSymbolAddress((void**)&gAsym, g_Asym);
    cudaGetSymbolAddress((void**)&gB, g_Bm);
    cudaGetSymbolAddress((void**)&gV, g_V);

    cudaFuncSetAttribute(k_cholinv, cudaFuncAttributeMaxDynamicSharedMemorySize, CHOL_SMEM);
    cudaFuncSetAttribute(k_gemm<0, RR>, cudaFuncAttributeMaxDynamicSharedMemorySize, GEMM_SMEM);
    cudaFuncSetAttribute(k_gemm<2, CC>, cudaFuncAttributeMaxDynamicSharedMemorySize, GEMM_SMEM);
    cudaFuncSetAttribute(k_gemm<3, CC>, cudaFuncAttributeMaxDynamicSharedMemorySize, GEMM_SMEM);

    dim3 blk(256);

    // 1) A = M^T Graw
    k_gemm<0, RR><<<dim3(2, 2, NB), blk, GEMM_SMEM>>>(M, Mg, nullptr, nullptr, lr, s_lr, gA);
    // 2) Asym = 0.5*(A + A^T)
    k_sym<<<(NB * 65536) / 256, blk>>>(gA, gAsym);
    // 3) B = M + a*(M@Asym - U - Graw)
    k_gemm<2, CC><<<dim3(2, 18, NB), blk, GEMM_SMEM>>>(M, gAsym, Up, Mg, lr, s_lr, gB);
    // 4) S = B^T B
    k_gemm<0, RR><<<dim3(2, 2, NB), blk, GEMM_SMEM>>>(gB, gB, nullptr, nullptr, lr, s_lr, gA);
    // 5) blocked Cholesky + triangular inverse -> V = R^{-1}
    k_cholinv<<<NB, blk, CHOL_SMEM>>>(gA, gV);
    // 6) out[b][c][r] = sum_k B[r][k] V[k][c]
    k_gemm<3, CC><<<dim3(2, 18, NB), blk, GEMM_SMEM>>>(gB, gV, nullptr, nullptr, lr, s_lr, out);
}

// round 6
// speedup vs baseline: 3.0322x; 1.1016x over previous
#include <cuda_runtime.h>
#include <cuda_bf16.h>
#include <cstdint>
#include <math.h>

// Batched Stiefel optimizer step via Cholesky-QR.
// Round 6: ldmatrix.x4 fragment loads (issue-slot bound -> fewer instructions),
// symmetric-output GEMM4 (3 tiles/batch instead of 4).

#define NB 128
#define RR 2304
#define CC 256

__device__ float g_A[(size_t)NB * CC * CC];     // A = M^T Graw, later S = B^T B
__device__ float g_Asym[(size_t)NB * CC * CC];  // sym(A)
__device__ float g_Bm[(size_t)NB * RR * CC];    // B = M + P
__device__ float g_V[(size_t)NB * CC * CC];     // V = R^{-1} dense upper

// ---------------------------------------------------------------------------
static constexpr int HROWB = 80;                 // smem row bytes; 20 words -> conflict-free
static constexpr int BUF = 128 * HROWB;
static constexpr int OFF_AH = 0;
static constexpr int OFF_AL = BUF;
static constexpr int OFF_BH = 2 * BUF;
static constexpr int OFF_BL = 3 * BUF;
static constexpr int STAGE_BYTES = 4 * BUF;      // 40960
static constexpr int GEMM_SMEM = 2 * STAGE_BYTES;

__device__ __forceinline__ uint32_t smem_u32(const void* p) {
    uint32_t a;
    asm("{ .reg .u64 t; cvta.to.shared.u64 t, %1; cvt.u32.u64 %0, t; }"
        : "=r"(a) : "l"(p));
    return a;
}

__device__ __forceinline__ void mma16816(float* c, const uint32_t* a, const uint32_t* b) {
    asm volatile(
        "mma.sync.aligned.m16n8k16.row.col.f32.bf16.bf16.f32 "
        "{%0,%1,%2,%3}, {%4,%5,%6,%7}, {%8,%9}, {%0,%1,%2,%3};"
        : "+f"(c[0]), "+f"(c[1]), "+f"(c[2]), "+f"(c[3])
        : "r"(a[0]), "r"(a[1]), "r"(a[2]), "r"(a[3]), "r"(b[0]), "r"(b[1]));
}

__device__ __forceinline__ void ldsm4(uint32_t& r0, uint32_t& r1, uint32_t& r2,
                                      uint32_t& r3, uint32_t addr) {
    asm volatile("ldmatrix.sync.aligned.m8n8.x4.shared.b16 {%0,%1,%2,%3}, [%4];"
                 : "=r"(r0), "=r"(r1), "=r"(r2), "=r"(r3) : "r"(addr));
}

__device__ __forceinline__ void split2(float x0, float x1, uint32_t& h, uint32_t& l) {
    __nv_bfloat16 h0 = __float2bfloat16(x0), h1 = __float2bfloat16(x1);
    float r0 = x0 - __bfloat162float(h0);
    float r1 = x1 - __bfloat162float(h1);
    __nv_bfloat16 l0 = __float2bfloat16(r0), l1 = __float2bfloat16(r1);
    h = ((uint32_t)__bfloat16_as_ushort(h1) << 16) | __bfloat16_as_ushort(h0);
    l = ((uint32_t)__bfloat16_as_ushort(l1) << 16) | __bfloat16_as_ushort(l0);
}

// ---------------------------------------------------------------------------
// Unified GEMM. 128x128 CTA tile, split-bf16 3-product, mma.sync + ldmatrix.
// MODE 0 (TN, K=KTOT): D -> Op[i0+m][j0+n] (256x256). TRI: only lower tiles.
// MODE 2 (NN, K=256):  Op = Ag + a*(D - E1 - E2)   (B-build)
// MODE 3 (NN, K=256):  Op[j0+n][i0+m] = D (transposed)
// ---------------------------------------------------------------------------
template <int MODE, int KTOT, bool TRI>
__global__ void __launch_bounds__(256, 2)
k_gemm(const float* __restrict__ Ag_, const float* __restrict__ Bg_,
       const float* __restrict__ E1_, const float* __restrict__ E2_,
       const float* __restrict__ lr, const float* __restrict__ s_lr,
       float* __restrict__ Out)
{
    extern __shared__ char dsm[];
    const int tid = threadIdx.x;
    const int lane = tid & 31, warp = tid >> 5;
    const int wm = warp & 3, wn = warp >> 2;
    const int b = blockIdx.z;

    int i0, j0;
    if (TRI) {
        int bx = blockIdx.x;            // 0:(0,0) 1:(1,0) 2:(1,1)
        i0 = (bx >= 1) ? 128 : 0;
        j0 = (bx == 2) ? 128 : 0;
    } else {
        j0 = blockIdx.x * 128;
        i0 = blockIdx.y * 128;
    }

    const size_t bigS = (size_t)RR * CC, smlS = (size_t)CC * CC;
    const float* Ag = Ag_ + (size_t)b * bigS;
    const float* Bg = Bg_ + (size_t)b * ((MODE == 0) ? bigS : smlS);
    float* Op = Out + (size_t)b * ((MODE == 0) ? smlS : bigS);

    const uint32_t base32 = smem_u32(dsm);

    float acc[2][8][4] = {};
    float ra[16], rb[16];

    constexpr int NC = KTOT / 32;

    auto LOADR = [&](int c) {
        const int k0 = c * 32;
        if (MODE == 0) {
#pragma unroll
            for (int it = 0; it < 4; ++it) {
                int idx = tid + it * 256;
                int m = idx & 127, kq = idx >> 7;
#pragma unroll
                for (int j = 0; j < 4; ++j)
                    ra[it * 4 + j] = Ag[(size_t)(k0 + kq * 4 + j) * CC + i0 + m];
            }
        } else {
#pragma unroll
            for (int it = 0; it < 4; ++it) {
                int idx = tid + it * 256;
                int kq = idx & 7, m = idx >> 3;
                float4 v = *(const float4*)(Ag + (size_t)(i0 + m) * CC + k0 + kq * 4);
                ra[it * 4 + 0] = v.x; ra[it * 4 + 1] = v.y;
                ra[it * 4 + 2] = v.z; ra[it * 4 + 3] = v.w;
            }
        }
#pragma unroll
        for (int it = 0; it < 4; ++it) {
            int idx = tid + it * 256;
            int n = idx & 127, kq = idx >> 7;
#pragma unroll
            for (int j = 0; j < 4; ++j)
                rb[it * 4 + j] = Bg[(size_t)(k0 + kq * 4 + j) * CC + j0 + n];
        }
    };

    auto STORER = [&](int s) {
        char* st = dsm + s * STAGE_BYTES;
#pragma unroll
        for (int it = 0; it < 4; ++it) {
            int idx = tid + it * 256;
            int m, kq;
            if (MODE == 0) { m = idx & 127; kq = idx >> 7; }
            else           { kq = idx & 7;  m = idx >> 3; }
            uint32_t h01, l01, h23, l23;
            split2(ra[it * 4 + 0], ra[it * 4 + 1], h01, l01);
            split2(ra[it * 4 + 2], ra[it * 4 + 3], h23, l23);
            *(uint2*)(st + OFF_AH + m * HROWB + kq * 8) = make_uint2(h01, h23);
            *(uint2*)(st + OFF_AL + m * HROWB + kq * 8) = make_uint2(l01, l23);
        }
#pragma unroll
        for (int it = 0; it < 4; ++it) {
            int idx = tid + it * 256;
            int n = idx & 127, kq = idx >> 7;
            uint32_t h01, l01, h23, l23;
            split2(rb[it * 4 + 0], rb[it * 4 + 1], h01, l01);
            split2(rb[it * 4 + 2], rb[it * 4 + 3], h23, l23);
            *(uint2*)(st + OFF_BH + n * HROWB + kq * 8) = make_uint2(h01, h23);
            *(uint2*)(st + OFF_BL + n * HROWB + kq * 8) = make_uint2(l01, l23);
        }
    };

    // Fragment loads via ldmatrix.x4 on the 80B-pitch layout (conflict-free).
    auto COMPUTE = [&](int s) {
        const uint32_t st = base32 + s * STAGE_BYTES;
#pragma unroll
        for (int ks = 0; ks < 2; ++ks) {
            const uint32_t kb = ks * 32;   // byte offset of this k16 group
            uint32_t ah[2][4], al[2][4], bh[8][2], bl[8][2];
            // A frags: lanes 0-15 chunk kb (rows 0-7 tile0, 8-15 tile1),
            //          lanes 16-31 chunk kb+16 (tiles 2,3) -> {a0,a1,a2,a3}
            const int arow_off = (lane & 15);
            const uint32_t achunk = kb + ((lane >> 4) << 4);
#pragma unroll
            for (int mi = 0; mi < 2; ++mi) {
                uint32_t rowa = (uint32_t)(wm * 32 + mi * 16 + arow_off) * HROWB + achunk;
                ldsm4(ah[mi][0], ah[mi][1], ah[mi][2], ah[mi][3], st + OFF_AH + rowa);
                ldsm4(al[mi][0], al[mi][1], al[mi][2], al[mi][3], st + OFF_AL + rowa);
            }
            // B frags: lanes 0-7 rows n0-7 @kb, 8-15 rows n0-7 @kb+16,
            //          16-23 rows n8-15 @kb, 24-31 rows n8-15 @kb+16
            const int brow_off = (lane & 7) + ((lane >> 4) << 3);
            const uint32_t bchunk = kb + (((lane >> 3) & 1) << 4);
#pragma unroll
            for (int p = 0; p < 4; ++p) {
                uint32_t rowb = (uint32_t)(wn * 64 + p * 16 + brow_off) * HROWB + bchunk;
                ldsm4(bh[2 * p][0], bh[2 * p][1], bh[2 * p + 1][0], bh[2 * p + 1][1],
                      st + OFF_BH + rowb);
                ldsm4(bl[2 * p][0], bl[2 * p][1], bl[2 * p + 1][0], bl[2 * p + 1][1],
                      st + OFF_BL + rowb);
            }
#pragma unroll
            for (int mi = 0; mi < 2; ++mi)
#pragma unroll
                for (int ni = 0; ni < 8; ++ni) {
                    mma16816(acc[mi][ni], ah[mi], bh[ni]);
                    mma16816(acc[mi][ni], al[mi], bh[ni]);
                    mma16816(acc[mi][ni], ah[mi], bl[ni]);
                }
        }
    };

    LOADR(0);
    STORER(0);
    __syncthreads();
    for (int c = 0; c < NC; ++c) {
        if (c + 1 < NC) LOADR(c + 1);
        COMPUTE(c & 1);
        if (c + 1 < NC) STORER((c + 1) & 1);
        __syncthreads();
    }

    const int g = lane >> 2, tg = lane & 3;
    if (MODE == 0) {
#pragma unroll
        for (int mi = 0; mi < 2; ++mi)
#pragma unroll
            for (int ni = 0; ni < 8; ++ni) {
                int row = i0 + wm * 32 + mi * 16 + g;
                int col = j0 + wn * 64 + ni * 8 + tg * 2;
                *(float2*)(Op + (size_t)row * CC + col) =
                    make_float2(acc[mi][ni][0], acc[mi][ni][1]);
                *(float2*)(Op + (size_t)(row + 8) * CC + col) =
                    make_float2(acc[mi][ni][2], acc[mi][ni][3]);
            }
    } else if (MODE == 2) {
        const float aSc = fabsf(lr[b]) * s_lr[0];
        const float* E1 = E1_ + (size_t)b * bigS;
        const float* E2 = E2_ + (size_t)b * bigS;
#pragma unroll
        for (int mi = 0; mi < 2; ++mi)
#pragma unroll
            for (int ni = 0; ni < 8; ++ni) {
                int row = i0 + wm * 32 + mi * 16 + g;
                int col = j0 + wn * 64 + ni * 8 + tg * 2;
#pragma unroll
                for (int h = 0; h < 2; ++h) {
                    size_t o = (size_t)(row + 8 * h) * CC + col;
                    float2 mv = *(const float2*)(Ag + o);
                    float2 uv = *(const float2*)(E1 + o);
                    float2 gv = *(const float2*)(E2 + o);
                    float2 r;
                    r.x = mv.x + aSc * (acc[mi][ni][2 * h + 0] - uv.x - gv.x);
                    r.y = mv.y + aSc * (acc[mi][ni][2 * h + 1] - uv.y - gv.y);
                    *(float2*)(Op + o) = r;
                }
            }
    } else {
        const int TP = 132;
        float* T = (float*)dsm;
#pragma unroll
        for (int mi = 0; mi < 2; ++mi)
#pragma unroll
            for (int ni = 0; ni < 8; ++ni) {
                int ml = wm * 32 + mi * 16 + g;
                int nl = wn * 64 + ni * 8 + tg * 2;
                T[nl * TP + ml]           = acc[mi][ni][0];
                T[(nl + 1) * TP + ml]     = acc[mi][ni][1];
                T[nl * TP + ml + 8]       = acc[mi][ni][2];
                T[(nl + 1) * TP + ml + 8] = acc[mi][ni][3];
            }
        __syncthreads();
        int n = tid >> 1, sh = (tid & 1) * 64;
        const float* src = T + n * TP + sh;
        float* dst = Op + (size_t)(j0 + n) * RR + i0 + sh;
#pragma unroll
        for (int q = 0; q < 16; ++q)
            *(float4*)(dst + q * 4) = *(const float4*)(src + q * 4);
    }
}

// ---------------------------------------------------------------------------
__global__ void k_sym(const float* __restrict__ A, float* __restrict__ Asym) {
    int idx = blockIdx.x * 256 + threadIdx.x;
    int b = idx >> 16;
    int rem = idx & 65535;
    int i = rem >> 8, j = rem & 255;
    size_t base = (size_t)b * 65536;
    Asym[base + rem] = 0.5f * (A[base + i * 256 + j] + A[base + j * 256 + i]);
}

// ---------------------------------------------------------------------------
// Blocked Cholesky (panel=32) + blocked triangular inverse (packed lower).
// ---------------------------------------------------------------------------
__device__ __forceinline__ int tri(int r) { return (r * (r + 1)) >> 1; }

static constexpr int CHOL_SMEM = (32896 + 8704) * 4;

__global__ void __launch_bounds__(256, 1)
k_cholinv(const float* __restrict__ S, float* __restrict__ V)
{
    extern __shared__ float sm[];
    float* Lp = sm;
    float* P  = sm + 32896;

    const int b = blockIdx.x;
    const int tid = threadIdx.x;
    const float* Sp = S + (size_t)b * 65536;

    for (int i = 0; i < 256; i++)
        if (tid <= i) Lp[tri(i) + tid] = Sp[(size_t)i * 256 + tid];
    __syncthreads();

    for (int p = 0; p < 8; ++p) {
        const int c0 = 32 * p, rows = 256 - c0;

        for (int idx = tid; idx < rows * 32; idx += 256) {
            int lr = idx >> 5, c = idx & 31;
            int r = c0 + lr, gc = c0 + c;
            P[lr * 34 + c] = (gc <= r) ? Lp[tri(r) + gc] : 0.0f;
        }
        __syncthreads();

        for (int j = 0; j < 32; ++j) {
            if (tid == 0) P[j * 34 + j] = sqrtf(P[j * 34 + j]);
            __syncthreads();
            if (tid < 32 && tid > j) P[tid * 34 + j] /= P[j * 34 + j];
            __syncthreads();
            if (tid < 32 && tid > j) {
                float lij = P[tid * 34 + j];
                for (int k = j + 1; k <= tid; ++k)
                    P[tid * 34 + k] -= lij * P[k * 34 + j];
            }
            __syncthreads();
        }

        {
            int nr = rows - 32;
            if (tid < nr) {
                int lr = 32 + tid;
                float x[32];
#pragma unroll
                for (int c = 0; c < 32; ++c) x[c] = P[lr * 34 + c];
#pragma unroll
                for (int j = 0; j < 32; ++j) {
                    float s = x[j];
#pragma unroll
                    for (int k = 0; k < j; ++k) s -= x[k] * P[j * 34 + k];
                    x[j] = s / P[j * 34 + j];
                }
                int rb = tri(c0 + lr) + c0;
#pragma unroll
                for (int c = 0; c < 32; ++c) { P[lr * 34 + c] = x[c]; Lp[rb + c] = x[c]; }
            }
            if (tid < 32) {
                int rb = tri(c0 + tid) + c0;
                for (int c = 0; c <= tid; ++c) Lp[rb + c] = P[tid * 34 + c];
            }
        }
        __syncthreads();

        int T = rows - 32;
        if (T > 0) {
            int Tb = T >> 1;
            int ntask = (Tb * (Tb + 1)) >> 1;
            for (int t = tid; t < ntask; t += 256) {
                int bi = (int)((sqrtf(8.0f * (float)t + 1.0f) - 1.0f) * 0.5f);
                while (((bi + 1) * (bi + 2)) / 2 <= t) ++bi;
                while ((bi * (bi + 1)) / 2 > t) --bi;
                int bj = t - (bi * (bi + 1)) / 2;
                int i0 = 32 + 2 * bi, j0 = 32 + 2 * bj;
                const float* Pi0 = P + i0 * 34;
                const float* Pi1 = Pi0 + 34;
                const float* Pj0 = P + j0 * 34;
                const float* Pj1 = Pj0 + 34;
                float a00 = 0, a01 = 0, a10 = 0, a11 = 0;
#pragma unroll
                for (int q = 0; q < 32; q += 2) {
                    float2 vi0 = *(const float2*)(Pi0 + q), vi1 = *(const float2*)(Pi1 + q);
                    float2 vj0 = *(const float2*)(Pj0 + q), vj1 = *(const float2*)(Pj1 + q);
                    a00 += vi0.x * vj0.x + vi0.y * vj0.y;
                    a01 += vi0.x * vj1.x + vi0.y * vj1.y;
                    a10 += vi1.x * vj0.x + vi1.y * vj0.y;
                    a11 += vi1.x * vj1.x + vi1.y * vj1.y;
                }
                int gr0 = c0 + i0, gr1 = gr0 + 1, gc0 = c0 + j0, gc1 = gc0 + 1;
                int rb0 = tri(gr0), rb1 = tri(gr1);
                Lp[rb0 + gc0] -= a00;
                if (bj < bi) Lp[rb0 + gc1] -= a01;
                Lp[rb1 + gc0] -= a10;
                Lp[rb1 + gc1] -= a11;
            }
        }
        __syncthreads();
    }

    {
        int w = tid >> 5, j = tid & 31;
        int g0 = 32 * w;
        float wc[32];
#pragma unroll
        for (int i = 0; i < 32; ++i) {
            int rb = tri(g0 + i) + g0;
            float acc = 0.0f;
#pragma unroll
            for (int k = 0; k < i; ++k) acc += Lp[rb + k] * wc[k];
            wc[i] = (((i == j) ? 1.0f : 0.0f) - acc) / Lp[rb + i];
        }
        __syncthreads();
#pragma unroll
        for (int i = 0; i < 32; ++i)
            if (i >= j) Lp[tri(g0 + i) + g0 + j] = wc[i];
    }
    __syncthreads();

    {
        int ti = tid >> 4, tj = tid & 15;
        int r0 = 2 * ti, r1 = r0 + 1, cA = 2 * tj, cB = cA + 1;
        for (int J = 0; J < 8; ++J) {
            for (int I = J + 1; I < 8; ++I) {
                int lb0 = tri(32 * I + r0), lb1 = tri(32 * I + r1);
                float a00 = 0, a01 = 0, a10 = 0, a11 = 0;
                {
                    int la0 = lb0 + 32 * J, la1 = lb1 + 32 * J;
#pragma unroll 8
                    for (int k = 0; k < 32; ++k) {
                        float x0 = Lp[la0 + k], x1 = Lp[la1 + k];
                        int wb = tri(32 * J + k) + 32 * J;
                        float y0 = (k >= cA) ? Lp[wb + cA] : 0.0f;
                        float y1 = (k >= cB) ? Lp[wb + cB] : 0.0f;
                        a00 += x0 * y0; a01 += x0 * y1;
                        a10 += x1 * y0; a11 += x1 * y1;
                    }
                }
                for (int K = J + 1; K < I; ++K) {
                    int la0 = lb0 + 32 * K, la1 = lb1 + 32 * K;
#pragma unroll 8
                    for (int k = 0; k < 32; ++k) {
                        float x0 = Lp[la0 + k], x1 = Lp[la1 + k];
                        int wb = tri(32 * K + k) + 32 * J;
                        float y0 = Lp[wb + cA], y1 = Lp[wb + cB];
                        a00 += x0 * y0; a01 += x0 * y1;
                        a10 += x1 * y0; a11 += x1 * y1;
                    }
                }
                P[r0 * 33 + cA] = a00; P[r0 * 33 + cB] = a01;
                P[r1 * 33 + cA] = a10; P[r1 * 33 + cB] = a11;
                __syncthreads();
                float b00 = 0, b01 = 0, b10 = 0, b11 = 0;
                int db0 = lb0 + 32 * I, db1 = lb1 + 32 * I;
                for (int k = 0; k <= r1; ++k) {
                    float w0 = (k <= r0) ? Lp[db0 + k] : 0.0f;
                    float w1 = Lp[db1 + k];
                    float t0 = P[k * 33 + cA], t1 = P[k * 33 + cB];
                    b00 += w0 * t0; b01 += w0 * t1;
                    b10 += w1 * t0; b11 += w1 * t1;
                }
                __syncthreads();
                Lp[lb0 + 32 * J + cA] = -b00; Lp[lb0 + 32 * J + cB] = -b01;
                Lp[lb1 + 32 * J + cA] = -b10; Lp[lb1 + 32 * J + cB] = -b11;
                __syncthreads();
            }
        }
    }

    float* Vp = V + (size_t)b * 65536;
    for (int idx = tid; idx < 65536; idx += 256) {
        int k = idx >> 8, c = idx & 255;
        Vp[idx] = (c >= k) ? Lp[tri(c) + k] : 0.0f;
    }
}

// ---------------------------------------------------------------------------
extern "C" void kernel_launch(void* const* d_in, const int* in_sizes, int n_in,
                              void* d_out, int out_size)
{
    const float* M    = (const float*)d_in[0];
    const float* Mg   = (const float*)d_in[1];
    const float* Up   = (const float*)d_in[2];
    const float* lr   = (const float*)d_in[3];
    const float* s_lr = (const float*)d_in[4];
    float* out = (float*)d_out;

    float *gA, *gAsym, *gB, *gV;
    cudaGetSymbolAddress((void**)&gA, g_A);
    cudaGetSymbolAddress((void**)&gAsym, g_Asym);
    cudaGetSymbolAddress((void**)&gB, g_Bm);
    cudaGetSymbolAddress((void**)&gV, g_V);

    cudaFuncSetAttribute(k_cholinv, cudaFuncAttributeMaxDynamicSharedMemorySize, CHOL_SMEM);
    cudaFuncSetAttribute(k_gemm<0, RR, false>, cudaFuncAttributeMaxDynamicSharedMemorySize, GEMM_SMEM);
    cudaFuncSetAttribute(k_gemm<0, RR, true>,  cudaFuncAttributeMaxDynamicSharedMemorySize, GEMM_SMEM);
    cudaFuncSetAttribute(k_gemm<2, CC, false>, cudaFuncAttributeMaxDynamicSharedMemorySize, GEMM_SMEM);
    cudaFuncSetAttribute(k_gemm<3, CC, false>, cudaFuncAttributeMaxDynamicSharedMemorySize, GEMM_SMEM);

    dim3 blk(256);

    // 1) A = M^T Graw (full)
    k_gemm<0, RR, false><<<dim3(2, 2, NB), blk, GEMM_SMEM>>>(M, Mg, nullptr, nullptr, lr, s_lr, gA);
    // 2) Asym = 0.5*(A + A^T)
    k_sym<<<(NB * 65536) / 256, blk>>>(gA, gAsym);
    // 3) B = M + a*(M@Asym - U - Graw)
    k_gemm<2, CC, false><<<dim3(2, 18, NB), blk, GEMM_SMEM>>>(M, gAsym, Up, Mg, lr, s_lr, gB);
    // 4) S = B^T B (lower tiles only — cholinv reads lower triangle)
    k_gemm<0, RR, true><<<dim3(3, 1, NB), blk, GEMM_SMEM>>>(gB, gB, nullptr, nullptr, lr, s_lr, gA);
    // 5) blocked Cholesky + triangular inverse -> V = R^{-1}
    k_cholinv<<<NB, blk, CHOL_SMEM>>>(gA, gV);
    // 6) out[b][c][r] = sum_k B[r][k] V[k][c]
    k_gemm<3, CC, false><<<dim3(2, 18, NB), blk, GEMM_SMEM>>>(gB, gV, nullptr, nullptr, lr, s_lr, out);
}